// round 1
// baseline (speedup 1.0000x reference)
#include <cuda_runtime.h>
#include <math.h>

#define Bv 128
#define Tv 256
#define Hv 1024
#define Lv 2

typedef unsigned long long u64;

// ---------------- scratch (device globals; no allocations allowed) ----------
__device__ float g_xb0[(size_t)Bv * Tv * Hv];   // x @ Wi0, laid out [b][t][h] (same as x)
__device__ float g_h0[2][Bv * Hv];              // ping-pong layer-0 hidden state
__device__ float g_h1[2][Bv * Hv];              // ping-pong layer-1 hidden state
__device__ float g_bsum[Lv * Hv];               // bi[l] + bh[l]
__device__ float g_PA[8][(size_t)Bv * 3072];    // split-K partials for the wave GEMM

// ---------------- packed fp32x2 helpers (Blackwell FFMA2) -------------------
__device__ __forceinline__ u64 pack2(float x, float y) {
    u64 r; asm("mov.b64 %0, {%1,%2};" : "=l"(r) : "f"(x), "f"(y)); return r;
}
__device__ __forceinline__ void fma2(u64& d, u64 a, u64 b) {
    asm("fma.rn.f32x2 %0, %1, %2, %0;" : "+l"(d) : "l"(a), "l"(b));
}

// ---------------- SGEMM tile: C[128 x 64] = A[128 x K] * B[K x 64] ----------
// 128 threads, TM=TN=8, BK=16, double-buffered smem, f32x2 accumulation.
// Writes (overwrites) C.
__device__ __forceinline__ void gemm_tile_128x64(
    const float* __restrict__ A, int lda, int m0,
    const float* __restrict__ Bm, int ldb, int bn0,
    int k0, int nk,
    float* __restrict__ C, int ldc, int cn0)
{
    __shared__ float As[2][16][132];   // transposed [k][m], padded
    __shared__ float Bs[2][16][64];    // [k][n]

    const int tid = threadIdx.x;
    const int tx = tid & 7;    // column group (8 cols each)
    const int ty = tid >> 3;   // row group (8 rows each)

    const float* Ag = A + (size_t)m0 * lda + k0;
    const float* Bg = Bm + (size_t)k0 * ldb + bn0;

    u64 acc[8][4];
#pragma unroll
    for (int i = 0; i < 8; i++)
#pragma unroll
        for (int j = 0; j < 4; j++) acc[i][j] = 0ull;

    float4 avr[4];
    float4 bvr[2];

    // prologue: load k-tile 0
#pragma unroll
    for (int r = 0; r < 4; r++) {
        int idx = tid + r * 128; int row = idx >> 2, c4 = idx & 3;
        avr[r] = *(const float4*)(Ag + (size_t)row * lda + c4 * 4);
    }
#pragma unroll
    for (int r = 0; r < 2; r++) {
        int idx = tid + r * 128; int kk = idx >> 4, n4 = idx & 15;
        bvr[r] = *(const float4*)(Bg + (size_t)kk * ldb + n4 * 4);
    }
#pragma unroll
    for (int r = 0; r < 4; r++) {
        int idx = tid + r * 128; int row = idx >> 2, c4 = idx & 3;
        As[0][c4 * 4 + 0][row] = avr[r].x;
        As[0][c4 * 4 + 1][row] = avr[r].y;
        As[0][c4 * 4 + 2][row] = avr[r].z;
        As[0][c4 * 4 + 3][row] = avr[r].w;
    }
#pragma unroll
    for (int r = 0; r < 2; r++) {
        int idx = tid + r * 128; int kk = idx >> 4, n4 = idx & 15;
        *(float4*)&Bs[0][kk][n4 * 4] = bvr[r];
    }
    __syncthreads();

    for (int kt = 0; kt < nk; kt++) {
        int buf = kt & 1;
        if (kt + 1 < nk) {
            const float* Ag2 = Ag + (kt + 1) * 16;
            const float* Bg2 = Bg + (size_t)(kt + 1) * 16 * ldb;
#pragma unroll
            for (int r = 0; r < 4; r++) {
                int idx = tid + r * 128; int row = idx >> 2, c4 = idx & 3;
                avr[r] = *(const float4*)(Ag2 + (size_t)row * lda + c4 * 4);
            }
#pragma unroll
            for (int r = 0; r < 2; r++) {
                int idx = tid + r * 128; int kk = idx >> 4, n4 = idx & 15;
                bvr[r] = *(const float4*)(Bg2 + (size_t)kk * ldb + n4 * 4);
            }
        }
#pragma unroll
        for (int k = 0; k < 16; k++) {
            float4 a0 = *(const float4*)&As[buf][k][ty * 8];
            float4 a1 = *(const float4*)&As[buf][k][ty * 8 + 4];
            const ulonglong2* bp = (const ulonglong2*)&Bs[buf][k][tx * 8];
            ulonglong2 bb0 = bp[0];
            ulonglong2 bb1 = bp[1];
            u64 b0 = bb0.x, b1 = bb0.y, b2 = bb1.x, b3 = bb1.y;
            u64 ap[8];
            ap[0] = pack2(a0.x, a0.x); ap[1] = pack2(a0.y, a0.y);
            ap[2] = pack2(a0.z, a0.z); ap[3] = pack2(a0.w, a0.w);
            ap[4] = pack2(a1.x, a1.x); ap[5] = pack2(a1.y, a1.y);
            ap[6] = pack2(a1.z, a1.z); ap[7] = pack2(a1.w, a1.w);
#pragma unroll
            for (int i = 0; i < 8; i++) {
                fma2(acc[i][0], ap[i], b0);
                fma2(acc[i][1], ap[i], b1);
                fma2(acc[i][2], ap[i], b2);
                fma2(acc[i][3], ap[i], b3);
            }
        }
        if (kt + 1 < nk) {
            int nb = buf ^ 1;
#pragma unroll
            for (int r = 0; r < 4; r++) {
                int idx = tid + r * 128; int row = idx >> 2, c4 = idx & 3;
                As[nb][c4 * 4 + 0][row] = avr[r].x;
                As[nb][c4 * 4 + 1][row] = avr[r].y;
                As[nb][c4 * 4 + 2][row] = avr[r].z;
                As[nb][c4 * 4 + 3][row] = avr[r].w;
            }
#pragma unroll
            for (int r = 0; r < 2; r++) {
                int idx = tid + r * 128; int kk = idx >> 4, n4 = idx & 15;
                *(float4*)&Bs[nb][kk][n4 * 4] = bvr[r];
            }
        }
        __syncthreads();
    }

    // epilogue: packed pairs are (n, n+1) in order -> contiguous stores
#pragma unroll
    for (int i = 0; i < 8; i++) {
        float* crow = C + (size_t)(m0 + ty * 8 + i) * ldc + cn0 + tx * 8;
        ulonglong2 v0; v0.x = acc[i][0]; v0.y = acc[i][1];
        ulonglong2 v1; v1.x = acc[i][2]; v1.y = acc[i][3];
        *(ulonglong2*)(crow) = v0;
        *(ulonglong2*)(crow + 4) = v1;
    }
}

// ---------------- kernels ---------------------------------------------------

// init: bsum = bi + bh ; broadcast initial hidden states into both ping-pong bufs
__global__ void __launch_bounds__(256) k_init(const float* __restrict__ h0in,
                                              const float* __restrict__ bi,
                                              const float* __restrict__ bh)
{
    int idx = blockIdx.x * 256 + threadIdx.x;   // grid 512 -> 131072 threads
    if (idx < Lv * Hv) g_bsum[idx] = bi[idx] + bh[idx];
    int j = idx & (Hv - 1);
    float v0 = h0in[j];
    float v1 = h0in[Hv + j];
    g_h0[0][idx] = v0; g_h0[1][idx] = v0;
    g_h1[0][idx] = v1; g_h1[1][idx] = v1;
}

// precompute g_xb0 = x @ Wi[0]   (M = B*T = 32768, N = 1024, K = 1024)
__global__ void __launch_bounds__(128) k_pre(const float* __restrict__ x,
                                             const float* __restrict__ Wi)
{
    gemm_tile_128x64(x, Hv, blockIdx.x * 128,
                     Wi, Hv, blockIdx.y * 64,
                     0, 64,
                     g_xb0, Hv, blockIdx.y * 64);
}

// one wave: C[128 x 3072] split-K=8 into g_PA.
// cols [0,1024):   h0_prev @ Wh0     (layer0, t = w)
// cols [1024,2048): h0_prev @ Wi1    (layer1, t = w-1)
// cols [2048,3072): h1_prev @ Wh1    (layer1, t = w-1)
__global__ void __launch_bounds__(128) k_wave(int p,
                                              const float* __restrict__ Wh,
                                              const float* __restrict__ Wi)
{
    int ct = blockIdx.x % 48;
    int s  = blockIdx.x / 48;          // 0..7
    int n0 = ct * 64;
    int seg = n0 >> 10;
    int bn0 = n0 & 1023;
    const float* A  = (seg == 2) ? g_h1[p] : g_h0[p];
    const float* Bm = (seg == 0) ? Wh : (seg == 1 ? (Wi + Hv * Hv) : (Wh + Hv * Hv));
    gemm_tile_128x64(A, Hv, 0, Bm, Hv, bn0, s * 128, 8, g_PA[s], 3072, n0);
}

// finalize a wave: reduce split-K partials, add biases (+ xb0 for layer0), tanh,
// write new states + output row t = w-1.
__global__ void __launch_bounds__(256) k_fin(int w, float* __restrict__ out)
{
    int idx = blockIdx.x * 256 + threadIdx.x;   // 32768 threads
    int b = idx >> 8;
    int j = (idx & 255) << 2;
    int p = w & 1;

    if (w < Tv) {
        float4 a0 = make_float4(0.f, 0.f, 0.f, 0.f);
#pragma unroll
        for (int s = 0; s < 8; s++) {
            const float* pa = g_PA[s] + (size_t)b * 3072;
            float4 v = *(const float4*)(pa + j);
            a0.x += v.x; a0.y += v.y; a0.z += v.z; a0.w += v.w;
        }
        float4 xb = *(const float4*)&g_xb0[((size_t)b * Tv + w) * Hv + j];
        float4 bs = *(const float4*)&g_bsum[j];
        float4 r;
        r.x = tanhf(a0.x + xb.x + bs.x);
        r.y = tanhf(a0.y + xb.y + bs.y);
        r.z = tanhf(a0.z + xb.z + bs.z);
        r.w = tanhf(a0.w + xb.w + bs.w);
        *(float4*)&g_h0[p ^ 1][b * Hv + j] = r;
    }
    if (w >= 1) {
        float4 a1 = make_float4(0.f, 0.f, 0.f, 0.f);
#pragma unroll
        for (int s = 0; s < 8; s++) {
            const float* pa = g_PA[s] + (size_t)b * 3072;
            float4 v1 = *(const float4*)(pa + 1024 + j);
            float4 v2 = *(const float4*)(pa + 2048 + j);
            a1.x += v1.x + v2.x; a1.y += v1.y + v2.y;
            a1.z += v1.z + v2.z; a1.w += v1.w + v2.w;
        }
        float4 bs = *(const float4*)&g_bsum[Hv + j];
        float4 r;
        r.x = tanhf(a1.x + bs.x);
        r.y = tanhf(a1.y + bs.y);
        r.z = tanhf(a1.z + bs.z);
        r.w = tanhf(a1.w + bs.w);
        *(float4*)&g_h1[p ^ 1][b * Hv + j] = r;
        *(float4*)&out[(size_t)b * Tv * Hv + (size_t)(w - 1) * Hv + j] = r;
    }
}

// final hidden state h_n: [B, L, H] appended after output.
// h0 final is in g_h0[0] (last write at wave 255), h1 final in g_h1[1] (wave 256).
__global__ void __launch_bounds__(256) k_hn(float* __restrict__ out)
{
    int idx = blockIdx.x * 256 + threadIdx.x;   // B*L*H = 262144
    int b = idx >> 11;
    int rem = idx & 2047;
    float v = (rem < Hv) ? g_h0[0][b * Hv + rem]
                         : g_h1[1][b * Hv + (rem - Hv)];
    out[(size_t)Bv * Tv * Hv + idx] = v;
}

// ---------------- launcher ---------------------------------------------------
extern "C" void kernel_launch(void* const* d_in, const int* in_sizes, int n_in,
                              void* d_out, int out_size)
{
    (void)in_sizes; (void)n_in;
    const float* x  = (const float*)d_in[0];
    const float* h0 = (const float*)d_in[1];
    const float* Wi = (const float*)d_in[2];
    const float* bi = (const float*)d_in[3];
    const float* Wh = (const float*)d_in[4];
    const float* bh = (const float*)d_in[5];
    float* out = (float*)d_out;

    k_init<<<512, 256>>>(h0, bi, bh);
    k_pre<<<dim3(256, 16), 128>>>(x, Wi);

    for (int w = 0; w <= Tv; w++) {
        k_wave<<<384, 128>>>(w & 1, Wh, Wi);
        k_fin<<<128, 256>>>(w, out);
    }

    if (out_size >= Bv * Tv * Hv + Bv * Lv * Hv) {
        k_hn<<<1024, 256>>>(out);
    }
}

// round 3
// speedup vs baseline: 1.0801x; 1.0801x over previous
#include <cuda_runtime.h>
#include <math.h>

#define Bv 128
#define Tv 256
#define Hv 1024
#define Lv 2
#define GRID 128
#define NTHR 256

typedef unsigned long long u64;

// ---------------- scratch (device globals; no allocations allowed) ----------
__device__ float g_xb0[(size_t)Bv * Tv * Hv];   // x @ Wi0, laid out [b][t][h]
__device__ float g_h0[2][Bv * Hv];              // ping-pong layer-0 hidden state
__device__ float g_h1[2][Bv * Hv];              // ping-pong layer-1 hidden state
__device__ float g_bsum[Lv * Hv];               // bi[l] + bh[l]
__device__ float g_PA[8][(size_t)Bv * 3072];    // split-K partials for the wave GEMM

// grid barrier state
__device__ unsigned g_arrive;
__device__ unsigned g_gen;

// ---------------- packed fp32x2 helpers (Blackwell FFMA2) -------------------
__device__ __forceinline__ u64 pack2(float x, float y) {
    u64 r; asm("mov.b64 %0, {%1,%2};" : "=l"(r) : "f"(x), "f"(y)); return r;
}
__device__ __forceinline__ void fma2(u64& d, u64 a, u64 b) {
    asm("fma.rn.f32x2 %0, %1, %2, %0;" : "+l"(d) : "l"(a), "l"(b));
}

// ---------------- grid-wide spin barrier ------------------------------------
__device__ __forceinline__ void gbar(unsigned expect) {
    __threadfence();            // release: make this thread's writes L2-visible
    __syncthreads();
    if (threadIdx.x == 0) {
        unsigned a = atomicAdd(&g_arrive, 1u);
        if (a == GRID - 1) {
            atomicExch(&g_arrive, 0u);
            __threadfence();
            atomicAdd(&g_gen, 1u);
        } else {
            while (*(volatile unsigned*)&g_gen < expect) { __nanosleep(64); }
        }
        __threadfence();
    }
    __syncthreads();
}

// ---------------- SGEMM tile: C[128 x 64] = A[128 x K] * B[K x 64] ----------
// 256 threads, thread tile 8x4, BK=16, double-buffered smem, f32x2 accumulation.
// A is read with __ldcg (cross-CTA mutable); B (weights) via L1.
__device__ __forceinline__ void gemm_tile_128x64(
    const float* __restrict__ A, int lda, int m0,
    const float* __restrict__ Bm, int ldb, int bn0,
    int k0, int nk,
    float* __restrict__ C, int ldc, int cn0)
{
    __shared__ float As[2][16][132];   // transposed [k][m], padded
    __shared__ float Bs[2][16][64];    // [k][n]

    const int tid = threadIdx.x;
    const int tx = tid & 15;   // column group (4 cols each)
    const int ty = tid >> 4;   // row group (8 rows each)

    const float* Ag = A + (size_t)m0 * lda + k0;
    const float* Bg = Bm + (size_t)k0 * ldb + bn0;

    u64 acc[8][2];
#pragma unroll
    for (int i = 0; i < 8; i++) { acc[i][0] = 0ull; acc[i][1] = 0ull; }

    float4 avr[2];
    float4 bvr;

    // prologue: load k-tile 0
#pragma unroll
    for (int r = 0; r < 2; r++) {
        int idx = tid + r * 256; int row = idx >> 2, c4 = idx & 3;
        avr[r] = __ldcg((const float4*)(Ag + (size_t)row * lda + c4 * 4));
    }
    {
        int kk = tid >> 4, n4 = tid & 15;
        bvr = *(const float4*)(Bg + (size_t)kk * ldb + n4 * 4);
    }
#pragma unroll
    for (int r = 0; r < 2; r++) {
        int idx = tid + r * 256; int row = idx >> 2, c4 = idx & 3;
        As[0][c4 * 4 + 0][row] = avr[r].x;
        As[0][c4 * 4 + 1][row] = avr[r].y;
        As[0][c4 * 4 + 2][row] = avr[r].z;
        As[0][c4 * 4 + 3][row] = avr[r].w;
    }
    {
        int kk = tid >> 4, n4 = tid & 15;
        *(float4*)&Bs[0][kk][n4 * 4] = bvr;
    }
    __syncthreads();

    for (int kt = 0; kt < nk; kt++) {
        int buf = kt & 1;
        if (kt + 1 < nk) {
            const float* Ag2 = Ag + (kt + 1) * 16;
            const float* Bg2 = Bg + (size_t)(kt + 1) * 16 * ldb;
#pragma unroll
            for (int r = 0; r < 2; r++) {
                int idx = tid + r * 256; int row = idx >> 2, c4 = idx & 3;
                avr[r] = __ldcg((const float4*)(Ag2 + (size_t)row * lda + c4 * 4));
            }
            {
                int kk = tid >> 4, n4 = tid & 15;
                bvr = *(const float4*)(Bg2 + (size_t)kk * ldb + n4 * 4);
            }
        }
#pragma unroll
        for (int k = 0; k < 16; k++) {
            float4 a0 = *(const float4*)&As[buf][k][ty * 8];
            float4 a1 = *(const float4*)&As[buf][k][ty * 8 + 4];
            ulonglong2 bb = *(const ulonglong2*)&Bs[buf][k][tx * 4];
            u64 b0 = bb.x, b1 = bb.y;
            u64 ap[8];
            ap[0] = pack2(a0.x, a0.x); ap[1] = pack2(a0.y, a0.y);
            ap[2] = pack2(a0.z, a0.z); ap[3] = pack2(a0.w, a0.w);
            ap[4] = pack2(a1.x, a1.x); ap[5] = pack2(a1.y, a1.y);
            ap[6] = pack2(a1.z, a1.z); ap[7] = pack2(a1.w, a1.w);
#pragma unroll
            for (int i = 0; i < 8; i++) {
                fma2(acc[i][0], ap[i], b0);
                fma2(acc[i][1], ap[i], b1);
            }
        }
        if (kt + 1 < nk) {
            int nb = buf ^ 1;
#pragma unroll
            for (int r = 0; r < 2; r++) {
                int idx = tid + r * 256; int row = idx >> 2, c4 = idx & 3;
                As[nb][c4 * 4 + 0][row] = avr[r].x;
                As[nb][c4 * 4 + 1][row] = avr[r].y;
                As[nb][c4 * 4 + 2][row] = avr[r].z;
                As[nb][c4 * 4 + 3][row] = avr[r].w;
            }
            {
                int kk = tid >> 4, n4 = tid & 15;
                *(float4*)&Bs[nb][kk][n4 * 4] = bvr;
            }
        }
        __syncthreads();
    }

    // epilogue: packed pairs (n, n+1) contiguous -> one 16B store per row
#pragma unroll
    for (int i = 0; i < 8; i++) {
        float* crow = C + (size_t)(m0 + ty * 8 + i) * ldc + cn0 + tx * 4;
        ulonglong2 v; v.x = acc[i][0]; v.y = acc[i][1];
        *(ulonglong2*)(crow) = v;
    }
}

// ---------------- kernels ---------------------------------------------------

// init: bsum = bi + bh ; broadcast initial hidden; reset barrier state
__global__ void __launch_bounds__(256) k_init(const float* __restrict__ h0in,
                                              const float* __restrict__ bi,
                                              const float* __restrict__ bh)
{
    int idx = blockIdx.x * 256 + threadIdx.x;   // grid 512 -> 131072 threads
    if (idx == 0) { g_arrive = 0u; g_gen = 0u; }
    if (idx < Lv * Hv) g_bsum[idx] = bi[idx] + bh[idx];
    int j = idx & (Hv - 1);
    float v0 = h0in[j];
    float v1 = h0in[Hv + j];
    g_h0[0][idx] = v0; g_h0[1][idx] = v0;
    g_h1[0][idx] = v1; g_h1[1][idx] = v1;
}

// precompute g_xb0 = x @ Wi[0]   (M = B*T = 32768, N = 1024, K = 1024)
__global__ void __launch_bounds__(NTHR) k_pre(const float* __restrict__ x,
                                              const float* __restrict__ Wi)
{
    gemm_tile_128x64(x, Hv, blockIdx.x * 128,
                     Wi, Hv, blockIdx.y * 64,
                     0, 64,
                     g_xb0, Hv, blockIdx.y * 64);
}

// persistent wavefront kernel: 257 waves, each = split-K GEMM + reduce/tanh,
// separated by grid-wide spin barriers.
// Wave GEMM C[128 x 3072], all K=1024:
//   cols [0,1024):    h0_prev @ Wh0     (layer0, t = w)
//   cols [1024,2048): h0_prev @ Wi1     (layer1, t = w-1)
//   cols [2048,3072): h1_prev @ Wh1     (layer1, t = w-1)
__global__ void __launch_bounds__(NTHR) k_persist(const float* __restrict__ Wh,
                                                  const float* __restrict__ Wi,
                                                  float* __restrict__ out)
{
    unsigned expect = 0;
    const int gid = blockIdx.x * NTHR + threadIdx.x;   // 0..32767

    for (int w = 0; w <= Tv; w++) {
        const int p = w & 1;

        // -------- phase 1: 3 GEMM items per CTA (384 items total) ----------
#pragma unroll 1
        for (int i = 0; i < 3; i++) {
            int id = blockIdx.x * 3 + i;      // 0..383
            int ct = id >> 3;                 // col tile 0..47
            int s  = id & 7;                  // K slice 0..7
            int seg = ct >> 4;
            int bn0 = (ct & 15) << 6;
            const float* Aa = (seg == 2) ? g_h1[p] : g_h0[p];
            const float* Bm = (seg == 0) ? Wh
                              : (seg == 1 ? (Wi + (size_t)Hv * Hv)
                                          : (Wh + (size_t)Hv * Hv));
            gemm_tile_128x64(Aa, Hv, 0, Bm, Hv, bn0, s * 128, 8,
                             g_PA[s], 3072, ct * 64);
        }
        gbar(++expect);

        // -------- phase 2: reduce split-K, bias, tanh, write states/out ----
        // exactly B*H/4 = 32768 float4 items == grid thread count (one each)
        {
            int idx = gid;                 // 0..32767
            int b = idx >> 8;              // 0..127
            int j = (idx & 255) << 2;      // 0..1020

            if (w < Tv) {
                float4 a0 = make_float4(0.f, 0.f, 0.f, 0.f);
#pragma unroll
                for (int s = 0; s < 8; s++) {
                    float4 v = __ldcg((const float4*)(g_PA[s] + (size_t)b * 3072 + j));
                    a0.x += v.x; a0.y += v.y; a0.z += v.z; a0.w += v.w;
                }
                float4 xb = *(const float4*)&g_xb0[((size_t)b * Tv + w) * Hv + j];
                float4 bs = *(const float4*)&g_bsum[j];
                float4 rr;
                rr.x = tanhf(a0.x + xb.x + bs.x);
                rr.y = tanhf(a0.y + xb.y + bs.y);
                rr.z = tanhf(a0.z + xb.z + bs.z);
                rr.w = tanhf(a0.w + xb.w + bs.w);
                *(float4*)&g_h0[p ^ 1][b * Hv + j] = rr;
            }
            if (w >= 1) {
                float4 a1 = make_float4(0.f, 0.f, 0.f, 0.f);
#pragma unroll
                for (int s = 0; s < 8; s++) {
                    const float* pa = g_PA[s] + (size_t)b * 3072;
                    float4 v1 = __ldcg((const float4*)(pa + 1024 + j));
                    float4 v2 = __ldcg((const float4*)(pa + 2048 + j));
                    a1.x += v1.x + v2.x; a1.y += v1.y + v2.y;
                    a1.z += v1.z + v2.z; a1.w += v1.w + v2.w;
                }
                float4 bs = *(const float4*)&g_bsum[Hv + j];
                float4 rr;
                rr.x = tanhf(a1.x + bs.x);
                rr.y = tanhf(a1.y + bs.y);
                rr.z = tanhf(a1.z + bs.z);
                rr.w = tanhf(a1.w + bs.w);
                *(float4*)&g_h1[p ^ 1][b * Hv + j] = rr;
                *(float4*)&out[(size_t)b * Tv * Hv + (size_t)(w - 1) * Hv + j] = rr;
            }
        }
        gbar(++expect);
    }
}

// final hidden state h_n: [B, L, H] appended after output.
// h0 final written at wave 255 -> g_h0[0]; h1 final at wave 256 -> g_h1[1].
__global__ void __launch_bounds__(256) k_hn(float* __restrict__ out)
{
    int idx = blockIdx.x * 256 + threadIdx.x;   // B*L*H = 262144
    int b = idx >> 11;
    int rem = idx & 2047;
    float v = (rem < Hv) ? g_h0[0][b * Hv + rem]
                         : g_h1[1][b * Hv + (rem - Hv)];
    out[(size_t)Bv * Tv * Hv + idx] = v;
}

// ---------------- launcher ---------------------------------------------------
extern "C" void kernel_launch(void* const* d_in, const int* in_sizes, int n_in,
                              void* d_out, int out_size)
{
    (void)in_sizes; (void)n_in;
    const float* x  = (const float*)d_in[0];
    const float* h0 = (const float*)d_in[1];
    const float* Wi = (const float*)d_in[2];
    const float* bi = (const float*)d_in[3];
    const float* Wh = (const float*)d_in[4];
    const float* bh = (const float*)d_in[5];
    float* out = (float*)d_out;

    k_init<<<512, 256>>>(h0, bi, bh);
    k_pre<<<dim3(256, 16), NTHR>>>(x, Wi);
    k_persist<<<GRID, NTHR>>>(Wh, Wi, out);

    if (out_size >= Bv * Tv * Hv + Bv * Lv * Hv) {
        k_hn<<<1024, 256>>>(out);
    }
}

// round 4
// speedup vs baseline: 1.0811x; 1.0009x over previous
#include <cuda_runtime.h>
#include <math.h>

#define Bv 128
#define Tv 256
#define Hv 1024
#define Lv 2
#define GRID 128
#define NTHR 256

typedef unsigned long long u64;

// ---------------- scratch (device globals; no allocations allowed) ----------
__device__ float g_xb0[(size_t)Bv * Tv * Hv];   // x @ Wi0, laid out [b][t][h]
__device__ float g_h0[2][Bv * Hv];              // ping-pong layer-0 hidden state
__device__ float g_h1[2][Bv * Hv];              // ping-pong layer-1 hidden state
__device__ float g_bsum[Lv * Hv];               // bi[l] + bh[l]
__device__ float g_PA[8][(size_t)Bv * 3072];    // split-K partials for the wave GEMM

// grid barrier state
__device__ unsigned g_arrive;
__device__ unsigned g_gen;

// ---------------- packed fp32x2 helpers (Blackwell FFMA2) -------------------
__device__ __forceinline__ u64 pack2(float x, float y) {
    u64 r; asm("mov.b64 %0, {%1,%2};" : "=l"(r) : "f"(x), "f"(y)); return r;
}
__device__ __forceinline__ void fma2(u64& d, u64 a, u64 b) {
    asm("fma.rn.f32x2 %0, %1, %2, %0;" : "+l"(d) : "l"(a), "l"(b));
}

// ---------------- grid-wide spin barrier ------------------------------------
__device__ __forceinline__ void gbar(unsigned expect) {
    __threadfence();            // release: make this thread's writes L2-visible
    __syncthreads();
    if (threadIdx.x == 0) {
        unsigned a = atomicAdd(&g_arrive, 1u);
        if (a == GRID - 1) {
            atomicExch(&g_arrive, 0u);
            __threadfence();
            atomicAdd(&g_gen, 1u);
        } else {
            while (*(volatile unsigned*)&g_gen < expect) { __nanosleep(64); }
        }
        __threadfence();
    }
    __syncthreads();
}

// ---------------- SGEMM tile: C[128 x 64] = A[128 x K] * B[K x 64] ----------
// 256 threads, thread tile 8x4, BK=16, double-buffered smem, f32x2 accumulation.
// A is read with __ldcg (cross-CTA mutable); B (weights) via L1.
__device__ __forceinline__ void gemm_tile_128x64(
    const float* __restrict__ A, int lda, int m0,
    const float* __restrict__ Bm, int ldb, int bn0,
    int k0, int nk,
    float* __restrict__ C, int ldc, int cn0)
{
    __shared__ float As[2][16][132];   // transposed [k][m], padded
    __shared__ float Bs[2][16][64];    // [k][n]

    const int tid = threadIdx.x;
    const int tx = tid & 15;   // column group (4 cols each)
    const int ty = tid >> 4;   // row group (8 rows each)

    const float* Ag = A + (size_t)m0 * lda + k0;
    const float* Bg = Bm + (size_t)k0 * ldb + bn0;

    u64 acc[8][2];
#pragma unroll
    for (int i = 0; i < 8; i++) { acc[i][0] = 0ull; acc[i][1] = 0ull; }

    float4 avr[2];
    float4 bvr;

    // prologue: load k-tile 0
#pragma unroll
    for (int r = 0; r < 2; r++) {
        int idx = tid + r * 256; int row = idx >> 2, c4 = idx & 3;
        avr[r] = __ldcg((const float4*)(Ag + (size_t)row * lda + c4 * 4));
    }
    {
        int kk = tid >> 4, n4 = tid & 15;
        bvr = *(const float4*)(Bg + (size_t)kk * ldb + n4 * 4);
    }
#pragma unroll
    for (int r = 0; r < 2; r++) {
        int idx = tid + r * 256; int row = idx >> 2, c4 = idx & 3;
        As[0][c4 * 4 + 0][row] = avr[r].x;
        As[0][c4 * 4 + 1][row] = avr[r].y;
        As[0][c4 * 4 + 2][row] = avr[r].z;
        As[0][c4 * 4 + 3][row] = avr[r].w;
    }
    {
        int kk = tid >> 4, n4 = tid & 15;
        *(float4*)&Bs[0][kk][n4 * 4] = bvr;
    }
    __syncthreads();

    for (int kt = 0; kt < nk; kt++) {
        int buf = kt & 1;
        if (kt + 1 < nk) {
            const float* Ag2 = Ag + (kt + 1) * 16;
            const float* Bg2 = Bg + (size_t)(kt + 1) * 16 * ldb;
#pragma unroll
            for (int r = 0; r < 2; r++) {
                int idx = tid + r * 256; int row = idx >> 2, c4 = idx & 3;
                avr[r] = __ldcg((const float4*)(Ag2 + (size_t)row * lda + c4 * 4));
            }
            {
                int kk = tid >> 4, n4 = tid & 15;
                bvr = *(const float4*)(Bg2 + (size_t)kk * ldb + n4 * 4);
            }
        }
#pragma unroll
        for (int k = 0; k < 16; k++) {
            float4 a0 = *(const float4*)&As[buf][k][ty * 8];
            float4 a1 = *(const float4*)&As[buf][k][ty * 8 + 4];
            ulonglong2 bb = *(const ulonglong2*)&Bs[buf][k][tx * 4];
            u64 b0 = bb.x, b1 = bb.y;
            u64 ap[8];
            ap[0] = pack2(a0.x, a0.x); ap[1] = pack2(a0.y, a0.y);
            ap[2] = pack2(a0.z, a0.z); ap[3] = pack2(a0.w, a0.w);
            ap[4] = pack2(a1.x, a1.x); ap[5] = pack2(a1.y, a1.y);
            ap[6] = pack2(a1.z, a1.z); ap[7] = pack2(a1.w, a1.w);
#pragma unroll
            for (int i = 0; i < 8; i++) {
                fma2(acc[i][0], ap[i], b0);
                fma2(acc[i][1], ap[i], b1);
            }
        }
        if (kt + 1 < nk) {
            int nb = buf ^ 1;
#pragma unroll
            for (int r = 0; r < 2; r++) {
                int idx = tid + r * 256; int row = idx >> 2, c4 = idx & 3;
                As[nb][c4 * 4 + 0][row] = avr[r].x;
                As[nb][c4 * 4 + 1][row] = avr[r].y;
                As[nb][c4 * 4 + 2][row] = avr[r].z;
                As[nb][c4 * 4 + 3][row] = avr[r].w;
            }
            {
                int kk = tid >> 4, n4 = tid & 15;
                *(float4*)&Bs[nb][kk][n4 * 4] = bvr;
            }
        }
        __syncthreads();
    }

    // epilogue: packed pairs (n, n+1) contiguous -> one 16B store per row
#pragma unroll
    for (int i = 0; i < 8; i++) {
        float* crow = C + (size_t)(m0 + ty * 8 + i) * ldc + cn0 + tx * 4;
        ulonglong2 v; v.x = acc[i][0]; v.y = acc[i][1];
        *(ulonglong2*)(crow) = v;
    }
}

// ---------------- kernels ---------------------------------------------------

// init: bsum = bi + bh ; broadcast initial hidden; reset barrier state
__global__ void __launch_bounds__(256) k_init(const float* __restrict__ h0in,
                                              const float* __restrict__ bi,
                                              const float* __restrict__ bh)
{
    int idx = blockIdx.x * 256 + threadIdx.x;   // grid 512 -> 131072 threads
    if (idx == 0) { g_arrive = 0u; g_gen = 0u; }
    if (idx < Lv * Hv) g_bsum[idx] = bi[idx] + bh[idx];
    int j = idx & (Hv - 1);
    float v0 = h0in[j];
    float v1 = h0in[Hv + j];
    g_h0[0][idx] = v0; g_h0[1][idx] = v0;
    g_h1[0][idx] = v1; g_h1[1][idx] = v1;
}

// precompute g_xb0 = x @ Wi[0]   (M = B*T = 32768, N = 1024, K = 1024)
__global__ void __launch_bounds__(NTHR) k_pre(const float* __restrict__ x,
                                              const float* __restrict__ Wi)
{
    gemm_tile_128x64(x, Hv, blockIdx.x * 128,
                     Wi, Hv, blockIdx.y * 64,
                     0, 64,
                     g_xb0, Hv, blockIdx.y * 64);
}

// persistent wavefront kernel: 257 waves, each = split-K GEMM + reduce/tanh,
// separated by grid-wide spin barriers.
// Wave GEMM C[128 x 3072], all K=1024:
//   cols [0,1024):    h0_prev @ Wh0     (layer0, t = w)
//   cols [1024,2048): h0_prev @ Wi1     (layer1, t = w-1)
//   cols [2048,3072): h1_prev @ Wh1     (layer1, t = w-1)
__global__ void __launch_bounds__(NTHR) k_persist(const float* __restrict__ Wh,
                                                  const float* __restrict__ Wi,
                                                  float* __restrict__ out)
{
    unsigned expect = 0;
    const int gid = blockIdx.x * NTHR + threadIdx.x;   // 0..32767

    for (int w = 0; w <= Tv; w++) {
        const int p = w & 1;

        // -------- phase 1: 3 GEMM items per CTA (384 items total) ----------
#pragma unroll 1
        for (int i = 0; i < 3; i++) {
            int id = blockIdx.x * 3 + i;      // 0..383
            int ct = id >> 3;                 // col tile 0..47
            int s  = id & 7;                  // K slice 0..7
            int seg = ct >> 4;
            int bn0 = (ct & 15) << 6;
            const float* Aa = (seg == 2) ? g_h1[p] : g_h0[p];
            const float* Bm = (seg == 0) ? Wh
                              : (seg == 1 ? (Wi + (size_t)Hv * Hv)
                                          : (Wh + (size_t)Hv * Hv));
            gemm_tile_128x64(Aa, Hv, 0, Bm, Hv, bn0, s * 128, 8,
                             g_PA[s], 3072, ct * 64);
        }
        gbar(++expect);

        // -------- phase 2: reduce split-K, bias, tanh, write states/out ----
        // exactly B*H/4 = 32768 float4 items == grid thread count (one each)
        {
            int idx = gid;                 // 0..32767
            int b = idx >> 8;              // 0..127
            int j = (idx & 255) << 2;      // 0..1020

            if (w < Tv) {
                float4 a0 = make_float4(0.f, 0.f, 0.f, 0.f);
#pragma unroll
                for (int s = 0; s < 8; s++) {
                    float4 v = __ldcg((const float4*)(g_PA[s] + (size_t)b * 3072 + j));
                    a0.x += v.x; a0.y += v.y; a0.z += v.z; a0.w += v.w;
                }
                float4 xb = *(const float4*)&g_xb0[((size_t)b * Tv + w) * Hv + j];
                float4 bs = *(const float4*)&g_bsum[j];
                float4 rr;
                rr.x = tanhf(a0.x + xb.x + bs.x);
                rr.y = tanhf(a0.y + xb.y + bs.y);
                rr.z = tanhf(a0.z + xb.z + bs.z);
                rr.w = tanhf(a0.w + xb.w + bs.w);
                *(float4*)&g_h0[p ^ 1][b * Hv + j] = rr;
            }
            if (w >= 1) {
                float4 a1 = make_float4(0.f, 0.f, 0.f, 0.f);
#pragma unroll
                for (int s = 0; s < 8; s++) {
                    const float* pa = g_PA[s] + (size_t)b * 3072;
                    float4 v1 = __ldcg((const float4*)(pa + 1024 + j));
                    float4 v2 = __ldcg((const float4*)(pa + 2048 + j));
                    a1.x += v1.x + v2.x; a1.y += v1.y + v2.y;
                    a1.z += v1.z + v2.z; a1.w += v1.w + v2.w;
                }
                float4 bs = *(const float4*)&g_bsum[Hv + j];
                float4 rr;
                rr.x = tanhf(a1.x + bs.x);
                rr.y = tanhf(a1.y + bs.y);
                rr.z = tanhf(a1.z + bs.z);
                rr.w = tanhf(a1.w + bs.w);
                *(float4*)&g_h1[p ^ 1][b * Hv + j] = rr;
                *(float4*)&out[(size_t)b * Tv * Hv + (size_t)(w - 1) * Hv + j] = rr;
            }
        }
        gbar(++expect);
    }
}

// final hidden state h_n: [B, L, H] appended after output.
// h0 final written at wave 255 -> g_h0[0]; h1 final at wave 256 -> g_h1[1].
__global__ void __launch_bounds__(256) k_hn(float* __restrict__ out)
{
    int idx = blockIdx.x * 256 + threadIdx.x;   // B*L*H = 262144
    int b = idx >> 11;
    int rem = idx & 2047;
    float v = (rem < Hv) ? g_h0[0][b * Hv + rem]
                         : g_h1[1][b * Hv + (rem - Hv)];
    out[(size_t)Bv * Tv * Hv + idx] = v;
}

// ---------------- launcher ---------------------------------------------------
extern "C" void kernel_launch(void* const* d_in, const int* in_sizes, int n_in,
                              void* d_out, int out_size)
{
    (void)in_sizes; (void)n_in;
    const float* x  = (const float*)d_in[0];
    const float* h0 = (const float*)d_in[1];
    const float* Wi = (const float*)d_in[2];
    const float* bi = (const float*)d_in[3];
    const float* Wh = (const float*)d_in[4];
    const float* bh = (const float*)d_in[5];
    float* out = (float*)d_out;

    k_init<<<512, 256>>>(h0, bi, bh);
    k_pre<<<dim3(256, 16), NTHR>>>(x, Wi);
    k_persist<<<GRID, NTHR>>>(Wh, Wi, out);

    if (out_size >= Bv * Tv * Hv + Bv * Lv * Hv) {
        k_hn<<<1024, 256>>>(out);
    }
}

// round 6
// speedup vs baseline: 2.0429x; 1.8896x over previous
#include <cuda_runtime.h>
#include <cuda_bf16.h>
#include <math.h>
#include <stdint.h>

#define Bv 128
#define Tv 256
#define Hv 1024
#define GRID 128
#define NTHR 256

// ---------------- scratch -----------------------------------------------------
__device__ __nv_bfloat16 g_xh[(size_t)Bv * Tv * Hv];
__device__ __nv_bfloat16 g_xl[(size_t)Bv * Tv * Hv];
__device__ __nv_bfloat16 g_Wth[4][(size_t)Hv * Hv];   // [n][k] hi: 0:Wh0 1:Wi1 2:Wh1 3:Wi0
__device__ __nv_bfloat16 g_Wtl[4][(size_t)Hv * Hv];   // [n][k] lo
__device__ __nv_bfloat16 g_h0h[2][Bv * Hv], g_h0l[2][Bv * Hv];
__device__ __nv_bfloat16 g_h1h[2][Bv * Hv], g_h1l[2][Bv * Hv];
__device__ float g_bsum[2 * Hv];
__device__ float g_C[(size_t)Bv * 4096];
__device__ unsigned g_arrive, g_gen;

// ---------------- smem layout (dynamic, 64 KB) ---------------------------------
#define OFF_AH(b) ((b) * 32768 + 0)
#define OFF_AL(b) ((b) * 32768 + 8192)
#define OFF_WH(b) ((b) * 32768 + 16384)
#define OFF_WL(b) ((b) * 32768 + 24576)
#define SMEM_SZ   65536

// ---------------- PTX helpers ---------------------------------------------------
__device__ __forceinline__ uint32_t smem_u32(const void* p) {
    uint32_t a;
    asm("{ .reg .u64 t; cvta.to.shared.u64 t, %1; cvt.u32.u64 %0, t; }" : "=r"(a) : "l"(p));
    return a;
}
__device__ __forceinline__ uint32_t swz(uint32_t o) { return o ^ ((o >> 3) & 0x70); }
__device__ __forceinline__ void cp16(uint32_t s, const void* g) {
    asm volatile("cp.async.cg.shared.global [%0], [%1], 16;" :: "r"(s), "l"(g));
}
__device__ __forceinline__ void ldm4(uint32_t* r, uint32_t addr) {
    asm volatile("ldmatrix.sync.aligned.m8n8.x4.shared.b16 {%0,%1,%2,%3}, [%4];"
        : "=r"(r[0]), "=r"(r[1]), "=r"(r[2]), "=r"(r[3]) : "r"(addr));
}
__device__ __forceinline__ void mma16816(float* c, const uint32_t* a, const uint32_t* b) {
    asm volatile("mma.sync.aligned.m16n8k16.row.col.f32.bf16.bf16.f32 "
        "{%0,%1,%2,%3}, {%4,%5,%6,%7}, {%8,%9}, {%0,%1,%2,%3};"
        : "+f"(c[0]), "+f"(c[1]), "+f"(c[2]), "+f"(c[3])
        : "r"(a[0]), "r"(a[1]), "r"(a[2]), "r"(a[3]), "r"(b[0]), "r"(b[1]));
}

// ---------------- grid barrier ----------------------------------------------------
__device__ __forceinline__ void gbar(unsigned expect) {
    __threadfence();
    __syncthreads();
    if (threadIdx.x == 0) {
        unsigned a = atomicAdd(&g_arrive, 1u);
        if (a == GRID - 1) {
            atomicExch(&g_arrive, 0u);
            __threadfence();
            atomicAdd(&g_gen, 1u);
        } else {
            while (*(volatile unsigned*)&g_gen < expect) { __nanosleep(64); }
        }
        __threadfence();
    }
    __syncthreads();
}

// ---------------- bf16 split helper ------------------------------------------------
__device__ __forceinline__ void split4(float4 v, uint2& uh, uint2& ul) {
    __nv_bfloat16 h0 = __float2bfloat16_rn(v.x), h1 = __float2bfloat16_rn(v.y);
    __nv_bfloat16 h2 = __float2bfloat16_rn(v.z), h3 = __float2bfloat16_rn(v.w);
    __nv_bfloat16 l0 = __float2bfloat16_rn(v.x - __bfloat162float(h0));
    __nv_bfloat16 l1 = __float2bfloat16_rn(v.y - __bfloat162float(h1));
    __nv_bfloat16 l2 = __float2bfloat16_rn(v.z - __bfloat162float(h2));
    __nv_bfloat16 l3 = __float2bfloat16_rn(v.w - __bfloat162float(h3));
    uh.x = (uint32_t)__bfloat16_as_ushort(h0) | ((uint32_t)__bfloat16_as_ushort(h1) << 16);
    uh.y = (uint32_t)__bfloat16_as_ushort(h2) | ((uint32_t)__bfloat16_as_ushort(h3) << 16);
    ul.x = (uint32_t)__bfloat16_as_ushort(l0) | ((uint32_t)__bfloat16_as_ushort(l1) << 16);
    ul.y = (uint32_t)__bfloat16_as_ushort(l2) | ((uint32_t)__bfloat16_as_ushort(l3) << 16);
}

// ---------------- prep kernels -------------------------------------------------------
__global__ void __launch_bounds__(256) k_init(const float* __restrict__ h0in,
                                              const float* __restrict__ bi,
                                              const float* __restrict__ bh)
{
    int idx = blockIdx.x * 256 + threadIdx.x;   // 512 blocks = Bv*Hv threads
    if (idx == 0) { g_arrive = 0u; g_gen = 0u; }
    if (idx < 2 * Hv) g_bsum[idx] = bi[idx] + bh[idx];
    int j = idx & (Hv - 1);
    float v0 = h0in[j], v1 = h0in[Hv + j];
    __nv_bfloat16 h = __float2bfloat16_rn(v0);
    __nv_bfloat16 l = __float2bfloat16_rn(v0 - __bfloat162float(h));
    g_h0h[0][idx] = h; g_h0l[0][idx] = l; g_h0h[1][idx] = h; g_h0l[1][idx] = l;
    h = __float2bfloat16_rn(v1);
    l = __float2bfloat16_rn(v1 - __bfloat162float(h));
    g_h1h[0][idx] = h; g_h1l[0][idx] = l; g_h1h[1][idx] = h; g_h1l[1][idx] = l;
}

__global__ void __launch_bounds__(256) k_splitx(const float* __restrict__ x)
{
    size_t i = (size_t)blockIdx.x * 256 + threadIdx.x;   // 32768 blocks
    float4 v = ((const float4*)x)[i];
    uint2 uh, ul;
    split4(v, uh, ul);
    ((uint2*)g_xh)[i] = uh;
    ((uint2*)g_xl)[i] = ul;
}

__global__ void k_splitw(const float* __restrict__ Wi, const float* __restrict__ Wh)
{
    __shared__ float t[32][33];
    int m = blockIdx.z;
    const float* W = (m == 0) ? Wh
                   : (m == 1) ? (Wi + (size_t)Hv * Hv)
                   : (m == 2) ? (Wh + (size_t)Hv * Hv) : Wi;
    int k0 = blockIdx.y * 32, n0 = blockIdx.x * 32;
    for (int r = threadIdx.y; r < 32; r += 8)
        t[r][threadIdx.x] = W[(size_t)(k0 + r) * Hv + n0 + threadIdx.x];
    __syncthreads();
    for (int r = threadIdx.y; r < 32; r += 8) {
        float v = t[threadIdx.x][r];
        __nv_bfloat16 h = __float2bfloat16_rn(v);
        __nv_bfloat16 l = __float2bfloat16_rn(v - __bfloat162float(h));
        size_t o = (size_t)(n0 + r) * Hv + k0 + threadIdx.x;
        g_Wth[m][o] = h;
        g_Wtl[m][o] = l;
    }
}

// ---------------- persistent wavefront kernel -----------------------------------------
// 128 CTAs: blockIdx = (col tile 0..63) * 2 + (row half 0..1). CTA tile: C[64, 64].
// seg = coltile>>4: 0: h0@Wh0   1: h0@Wi1   2: h1@Wh1   3: x_t@Wi0
__global__ void __launch_bounds__(NTHR)
k_persist(float* __restrict__ out, int has_hn)
{
    extern __shared__ char smem[];
    const uint32_t sb = smem_u32(smem);
    const int tid  = threadIdx.x;
    const int lane = tid & 31;
    const int wid  = tid >> 5;
    const int ctc  = blockIdx.x >> 1;          // col tile 0..63
    const int r0   = (blockIdx.x & 1) * 64;    // row half
    const int seg  = ctc >> 4;
    const int nloc = (ctc & 15) * 64;          // n offset within the seg's weight mat

    // warp tiling: 4 m-groups x 2 n-groups; warp tile m16 x n32
    const int wr = wid & 3, wc = wid >> 2;

    // ldmatrix per-lane address components (SW128 swizzle on 128B rows)
    const int mA    = wr * 16 + ((lane >> 3) & 1) * 8 + (lane & 7);
    const int koffA = ((lane >> 4) & 1) * 16;
    const uint32_t xorA  = (uint32_t)((mA & 7) * 16);
    const uint32_t abase = (uint32_t)(mA * 128);

    const int nW    = wc * 32 + ((lane >> 4) & 1) * 8 + (lane & 7);
    const int koffW = ((lane >> 3) & 1) * 16;
    const uint32_t xorW   = (uint32_t)((nW & 7) * 16);
    const uint32_t wbase0 = (uint32_t)(nW * 128);         // q=0 (n 0..15 of warp range)
    const uint32_t wbase1 = wbase0 + 16 * 128;            // q=1 (n 16..31)

    const __nv_bfloat16* Whb = g_Wth[seg] + (size_t)nloc * Hv;
    const __nv_bfloat16* Wlb = g_Wtl[seg] + (size_t)nloc * Hv;

    unsigned expect = 0;
    const int gid = blockIdx.x * NTHR + tid;   // 0..32767 == Bv*Hv/4

    for (int w = 0; w <= Tv; w++) {
        const int p = w & 1;
        const bool active = (seg == 1) || (seg == 2) || (w < Tv);

        if (active) {
            const __nv_bfloat16 *Ah, *Al;
            size_t astr;
            if (seg <= 1)      { Ah = g_h0h[p] + (size_t)r0 * Hv; Al = g_h0l[p] + (size_t)r0 * Hv; astr = Hv; }
            else if (seg == 2) { Ah = g_h1h[p] + (size_t)r0 * Hv; Al = g_h1l[p] + (size_t)r0 * Hv; astr = Hv; }
            else { Ah = g_xh + ((size_t)r0 * Tv + w) * Hv; Al = g_xl + ((size_t)r0 * Tv + w) * Hv; astr = (size_t)Tv * Hv; }

            auto load_tile = [&](uint32_t dst, const __nv_bfloat16* src, size_t rs) {
#pragma unroll
                for (int r = 0; r < 2; r++) {
                    int i = tid + r * 256;                 // 0..511
                    int row = i >> 3, kg = i & 7;
                    cp16(dst + swz(row * 128 + kg * 16), src + (size_t)row * rs + kg * 8);
                }
            };
            auto load_chunk = [&](int b, int c) {
                load_tile(sb + OFF_AH(b), Ah + c * 64, astr);
                load_tile(sb + OFF_AL(b), Al + c * 64, astr);
                load_tile(sb + OFF_WH(b), Whb + c * 64, Hv);
                load_tile(sb + OFF_WL(b), Wlb + c * 64, Hv);
                asm volatile("cp.async.commit_group;" ::: "memory");
            };

            float acc[4][4];
#pragma unroll
            for (int i = 0; i < 4; i++)
#pragma unroll
                for (int q = 0; q < 4; q++) acc[i][q] = 0.f;

            load_chunk(0, 0);
            load_chunk(1, 1);

#pragma unroll 1
            for (int c = 0; c < 16; c++) {
                const int b = c & 1;
                if (c < 15) asm volatile("cp.async.wait_group 1;" ::: "memory");
                else        asm volatile("cp.async.wait_group 0;" ::: "memory");
                __syncthreads();

                const uint32_t sAh = sb + OFF_AH(b) + abase;
                const uint32_t sAl = sb + OFF_AL(b) + abase;
                const uint32_t sW0h = sb + OFF_WH(b) + wbase0;
                const uint32_t sW1h = sb + OFF_WH(b) + wbase1;
                const uint32_t sW0l = sb + OFF_WL(b) + wbase0;
                const uint32_t sW1l = sb + OFF_WL(b) + wbase1;
#pragma unroll
                for (int kk = 0; kk < 4; kk++) {
                    uint32_t ka = ((uint32_t)(kk * 32 + koffA)) ^ xorA;
                    uint32_t kw = ((uint32_t)(kk * 32 + koffW)) ^ xorW;
                    uint32_t ah[4], al[4], wh[8], wl[8];
                    ldm4(ah, sAh + ka);
                    ldm4(al, sAl + ka);
                    ldm4(wh,     sW0h + kw);
                    ldm4(wh + 4, sW1h + kw);
                    ldm4(wl,     sW0l + kw);
                    ldm4(wl + 4, sW1l + kw);
#pragma unroll
                    for (int nt = 0; nt < 4; nt++) {
                        const uint32_t* bh = &wh[(nt >> 1) * 4 + (nt & 1) * 2];
                        const uint32_t* bl = &wl[(nt >> 1) * 4 + (nt & 1) * 2];
                        mma16816(acc[nt], ah, bh);
                        mma16816(acc[nt], al, bh);
                        mma16816(acc[nt], ah, bl);
                    }
                }
                __syncthreads();
                if (c + 2 < 16) load_chunk(b, c + 2);
            }

            // epilogue: write C tile
            const int g = lane >> 2, tq = lane & 3;
            float* Cb = g_C + (size_t)(r0 + wr * 16 + g) * 4096 + ctc * 64 + wc * 32 + tq * 2;
#pragma unroll
            for (int nt = 0; nt < 4; nt++) {
                float2 v0; v0.x = acc[nt][0]; v0.y = acc[nt][1];
                float2 v1; v1.x = acc[nt][2]; v1.y = acc[nt][3];
                *(float2*)(Cb + nt * 8) = v0;
                *(float2*)(Cb + 8 * 4096 + nt * 8) = v1;
            }
        }
        gbar(++expect);

        // ---------------- finalize ----------------
        {
            int idx = gid;                 // 0..32767, exactly Bv*Hv/4
            int bb = idx >> 8;
            int j  = (idx & 255) << 2;
            const float* Crow = g_C + (size_t)bb * 4096 + j;

            if (w < Tv) {
                float4 c0 = __ldcg((const float4*)(Crow));
                float4 c3 = __ldcg((const float4*)(Crow + 3072));
                float4 bs = *(const float4*)&g_bsum[j];
                float4 hv;
                hv.x = tanhf(c0.x + c3.x + bs.x);
                hv.y = tanhf(c0.y + c3.y + bs.y);
                hv.z = tanhf(c0.z + c3.z + bs.z);
                hv.w = tanhf(c0.w + c3.w + bs.w);
                uint2 uh, ul;
                split4(hv, uh, ul);
                *(uint2*)&g_h0h[p ^ 1][bb * Hv + j] = uh;
                *(uint2*)&g_h0l[p ^ 1][bb * Hv + j] = ul;
                if (w == Tv - 1 && has_hn)
                    *(float4*)&out[(size_t)Bv * Tv * Hv + (size_t)bb * 2 * Hv + j] = hv;
            }
            if (w >= 1) {
                float4 c1 = __ldcg((const float4*)(Crow + 1024));
                float4 c2 = __ldcg((const float4*)(Crow + 2048));
                float4 bs = *(const float4*)&g_bsum[Hv + j];
                float4 hv;
                hv.x = tanhf(c1.x + c2.x + bs.x);
                hv.y = tanhf(c1.y + c2.y + bs.y);
                hv.z = tanhf(c1.z + c2.z + bs.z);
                hv.w = tanhf(c1.w + c2.w + bs.w);
                uint2 uh, ul;
                split4(hv, uh, ul);
                *(uint2*)&g_h1h[p ^ 1][bb * Hv + j] = uh;
                *(uint2*)&g_h1l[p ^ 1][bb * Hv + j] = ul;
                *(float4*)&out[(size_t)bb * Tv * Hv + (size_t)(w - 1) * Hv + j] = hv;
                if (w == Tv && has_hn)
                    *(float4*)&out[(size_t)Bv * Tv * Hv + (size_t)bb * 2 * Hv + Hv + j] = hv;
            }
        }
        gbar(++expect);
    }
}

// ---------------- launcher -----------------------------------------------------------
extern "C" void kernel_launch(void* const* d_in, const int* in_sizes, int n_in,
                              void* d_out, int out_size)
{
    (void)in_sizes; (void)n_in;
    const float* x  = (const float*)d_in[0];
    const float* h0 = (const float*)d_in[1];
    const float* Wi = (const float*)d_in[2];
    const float* bi = (const float*)d_in[3];
    const float* Wh = (const float*)d_in[4];
    const float* bh = (const float*)d_in[5];
    float* out = (float*)d_out;

    cudaFuncSetAttribute(k_persist, cudaFuncAttributeMaxDynamicSharedMemorySize, SMEM_SZ);

    int has_hn = (out_size >= Bv * Tv * Hv + Bv * 2 * Hv) ? 1 : 0;

    k_init<<<512, 256>>>(h0, bi, bh);
    k_splitx<<<32768, 256>>>(x);
    k_splitw<<<dim3(32, 32, 4), dim3(32, 8)>>>(Wi, Wh);
    k_persist<<<GRID, NTHR, SMEM_SZ>>>(out, has_hn);
}

// round 7
// speedup vs baseline: 2.0770x; 1.0167x over previous
#include <cuda_runtime.h>
#include <cuda_bf16.h>
#include <math.h>
#include <stdint.h>

#define Bv 128
#define Tv 256
#define Hv 1024
#define GRID 128
#define NTHR 256

// ---------------- scratch -----------------------------------------------------
__device__ __nv_bfloat16 g_xh[(size_t)Bv * Tv * Hv];
__device__ __nv_bfloat16 g_xl[(size_t)Bv * Tv * Hv];
__device__ __nv_bfloat16 g_Wth[4][(size_t)Hv * Hv];   // [n][k] hi: 0:Wh0 1:Wi1 2:Wh1 3:Wi0
__device__ __nv_bfloat16 g_Wtl[4][(size_t)Hv * Hv];   // [n][k] lo
__device__ __nv_bfloat16 g_h0h[2][Bv * Hv], g_h0l[2][Bv * Hv];
__device__ __nv_bfloat16 g_h1h[2][Bv * Hv], g_h1l[2][Bv * Hv];
__device__ float g_bsum[2 * Hv];
__device__ float g_C[(size_t)Bv * 4096];
__device__ unsigned g_arrive, g_gen;

// ---------------- smem layout (dynamic) -----------------------------------------
// [0, 128K)   resident Wh slice: 16 chunk-tiles of 8KB (64 n-rows x 128B swizzled)
// [128K, ..)  double-buffered stream chunks: Ah | Al | Wl  (8KB each)
#define OFF_WRES  0
#define OFF_AH(b) (131072 + (b) * 24576)
#define OFF_AL(b) (131072 + (b) * 24576 + 8192)
#define OFF_WL(b) (131072 + (b) * 24576 + 16384)
#define OFF_CMB   OFF_AH(0)              // epilogue combine area (16KB, buffer 0 dead)
#define SMEM_SZ   180224

// ---------------- PTX helpers ---------------------------------------------------
__device__ __forceinline__ uint32_t smem_u32(const void* p) {
    uint32_t a;
    asm("{ .reg .u64 t; cvta.to.shared.u64 t, %1; cvt.u32.u64 %0, t; }" : "=r"(a) : "l"(p));
    return a;
}
__device__ __forceinline__ uint32_t swz(uint32_t o) { return o ^ ((o >> 3) & 0x70); }
__device__ __forceinline__ void cp16(uint32_t s, const void* g) {
    asm volatile("cp.async.cg.shared.global [%0], [%1], 16;" :: "r"(s), "l"(g));
}
__device__ __forceinline__ void ldm4(uint32_t* r, uint32_t addr) {
    asm volatile("ldmatrix.sync.aligned.m8n8.x4.shared.b16 {%0,%1,%2,%3}, [%4];"
        : "=r"(r[0]), "=r"(r[1]), "=r"(r[2]), "=r"(r[3]) : "r"(addr));
}
__device__ __forceinline__ void mma16816(float* c, const uint32_t* a, const uint32_t* b) {
    asm volatile("mma.sync.aligned.m16n8k16.row.col.f32.bf16.bf16.f32 "
        "{%0,%1,%2,%3}, {%4,%5,%6,%7}, {%8,%9}, {%0,%1,%2,%3};"
        : "+f"(c[0]), "+f"(c[1]), "+f"(c[2]), "+f"(c[3])
        : "r"(a[0]), "r"(a[1]), "r"(a[2]), "r"(a[3]), "r"(b[0]), "r"(b[1]));
}

// ---------------- grid barrier ----------------------------------------------------
__device__ __forceinline__ void gbar(unsigned expect) {
    __threadfence();
    __syncthreads();
    if (threadIdx.x == 0) {
        unsigned a = atomicAdd(&g_arrive, 1u);
        if (a == GRID - 1) {
            atomicExch(&g_arrive, 0u);
            __threadfence();
            atomicAdd(&g_gen, 1u);
        } else {
            while (*(volatile unsigned*)&g_gen < expect) { __nanosleep(64); }
        }
        __threadfence();
    }
    __syncthreads();
}

// ---------------- bf16 split helper ------------------------------------------------
__device__ __forceinline__ void split4(float4 v, uint2& uh, uint2& ul) {
    __nv_bfloat16 h0 = __float2bfloat16_rn(v.x), h1 = __float2bfloat16_rn(v.y);
    __nv_bfloat16 h2 = __float2bfloat16_rn(v.z), h3 = __float2bfloat16_rn(v.w);
    __nv_bfloat16 l0 = __float2bfloat16_rn(v.x - __bfloat162float(h0));
    __nv_bfloat16 l1 = __float2bfloat16_rn(v.y - __bfloat162float(h1));
    __nv_bfloat16 l2 = __float2bfloat16_rn(v.z - __bfloat162float(h2));
    __nv_bfloat16 l3 = __float2bfloat16_rn(v.w - __bfloat162float(h3));
    uh.x = (uint32_t)__bfloat16_as_ushort(h0) | ((uint32_t)__bfloat16_as_ushort(h1) << 16);
    uh.y = (uint32_t)__bfloat16_as_ushort(h2) | ((uint32_t)__bfloat16_as_ushort(h3) << 16);
    ul.x = (uint32_t)__bfloat16_as_ushort(l0) | ((uint32_t)__bfloat16_as_ushort(l1) << 16);
    ul.y = (uint32_t)__bfloat16_as_ushort(l2) | ((uint32_t)__bfloat16_as_ushort(l3) << 16);
}

// ---------------- prep kernels -------------------------------------------------------
__global__ void __launch_bounds__(256) k_init(const float* __restrict__ h0in,
                                              const float* __restrict__ bi,
                                              const float* __restrict__ bh)
{
    int idx = blockIdx.x * 256 + threadIdx.x;   // 512 blocks = Bv*Hv threads
    if (idx == 0) { g_arrive = 0u; g_gen = 0u; }
    if (idx < 2 * Hv) g_bsum[idx] = bi[idx] + bh[idx];
    int j = idx & (Hv - 1);
    float v0 = h0in[j], v1 = h0in[Hv + j];
    __nv_bfloat16 h = __float2bfloat16_rn(v0);
    __nv_bfloat16 l = __float2bfloat16_rn(v0 - __bfloat162float(h));
    g_h0h[0][idx] = h; g_h0l[0][idx] = l; g_h0h[1][idx] = h; g_h0l[1][idx] = l;
    h = __float2bfloat16_rn(v1);
    l = __float2bfloat16_rn(v1 - __bfloat162float(h));
    g_h1h[0][idx] = h; g_h1l[0][idx] = l; g_h1h[1][idx] = h; g_h1l[1][idx] = l;
}

__global__ void __launch_bounds__(256) k_splitx(const float* __restrict__ x)
{
    size_t i = (size_t)blockIdx.x * 256 + threadIdx.x;   // 32768 blocks
    float4 v = ((const float4*)x)[i];
    uint2 uh, ul;
    split4(v, uh, ul);
    ((uint2*)g_xh)[i] = uh;
    ((uint2*)g_xl)[i] = ul;
}

__global__ void k_splitw(const float* __restrict__ Wi, const float* __restrict__ Wh)
{
    __shared__ float t[32][33];
    int m = blockIdx.z;
    const float* W = (m == 0) ? Wh
                   : (m == 1) ? (Wi + (size_t)Hv * Hv)
                   : (m == 2) ? (Wh + (size_t)Hv * Hv) : Wi;
    int k0 = blockIdx.y * 32, n0 = blockIdx.x * 32;
    for (int r = threadIdx.y; r < 32; r += 8)
        t[r][threadIdx.x] = W[(size_t)(k0 + r) * Hv + n0 + threadIdx.x];
    __syncthreads();
    for (int r = threadIdx.y; r < 32; r += 8) {
        float v = t[threadIdx.x][r];
        __nv_bfloat16 h = __float2bfloat16_rn(v);
        __nv_bfloat16 l = __float2bfloat16_rn(v - __bfloat162float(h));
        size_t o = (size_t)(n0 + r) * Hv + k0 + threadIdx.x;
        g_Wth[m][o] = h;
        g_Wtl[m][o] = l;
    }
}

// ---------------- persistent wavefront kernel -----------------------------------------
// 128 CTAs: blockIdx = (col tile 0..63) * 2 + (row half 0..1). CTA tile C[64, 64].
// seg = coltile>>4: 0: h0@Wh0   1: h0@Wi1   2: h1@Wh1   3: x_t@Wi0
// Warps: tw = wid&3 -> (wr = tw&1: m32 half, wc = tw>>1: n32 half); khalf = wid>>2
// processes ksteps {0,1} or {2,3} of each k64 chunk. Partial accs combined in smem.
__global__ void __launch_bounds__(NTHR)
k_persist(float* __restrict__ out, int has_hn)
{
    extern __shared__ char smem[];
    const uint32_t sb = smem_u32(smem);
    const int tid  = threadIdx.x;
    const int lane = tid & 31;
    const int wid  = tid >> 5;
    const int ctc  = blockIdx.x >> 1;
    const int r0   = (blockIdx.x & 1) * 64;
    const int seg  = ctc >> 4;
    const int nloc = (ctc & 15) * 64;

    const int tw = wid & 3, khalf = wid >> 2;
    const int wr = tw & 1, wc = tw >> 1;

    // A fragment addressing (two m16 tiles at rows wr*32 and wr*32+16)
    const int mA    = wr * 32 + ((lane >> 3) & 1) * 8 + (lane & 7);
    const int koffA = ((lane >> 4) & 1) * 16;
    const uint32_t xorA   = (uint32_t)((mA & 7) * 16);
    const uint32_t abase0 = (uint32_t)(mA * 128);
    const uint32_t abase1 = (uint32_t)((mA + 16) * 128);   // (mA+16)&7 == mA&7

    // W fragment addressing (two n16 groups at wbase0/wbase1)
    const int nW    = wc * 32 + ((lane >> 4) & 1) * 8 + (lane & 7);
    const int koffW = ((lane >> 3) & 1) * 16;
    const uint32_t xorW   = (uint32_t)((nW & 7) * 16);
    const uint32_t wbase0 = (uint32_t)(nW * 128);
    const uint32_t wbase1 = wbase0 + 16 * 128;

    const __nv_bfloat16* Whb = g_Wth[seg] + (size_t)nloc * Hv;
    const __nv_bfloat16* Wlb = g_Wtl[seg] + (size_t)nloc * Hv;

    auto load_tile = [&](uint32_t dst, const __nv_bfloat16* src, size_t rs) {
#pragma unroll
        for (int r = 0; r < 2; r++) {
            int i = tid + r * 256;
            int row = i >> 3, kg = i & 7;
            cp16(dst + swz(row * 128 + kg * 16), src + (size_t)row * rs + kg * 8);
        }
    };

    // ---- load resident Wh slice (once for all waves) ----
    for (int c = 0; c < 16; c++)
        load_tile(sb + OFF_WRES + c * 8192, Whb + c * 64, Hv);
    asm volatile("cp.async.commit_group;" ::: "memory");
    asm volatile("cp.async.wait_group 0;" ::: "memory");
    __syncthreads();

    unsigned expect = 0;
    const int gid = blockIdx.x * NTHR + tid;   // 0..32767 == Bv*Hv/4

    for (int w = 0; w <= Tv; w++) {
        const int p = w & 1;
        const bool active = (seg == 1) || (seg == 2) || (w < Tv);

        if (active) {
            const __nv_bfloat16 *Ah, *Al;
            size_t astr;
            if (seg <= 1)      { Ah = g_h0h[p] + (size_t)r0 * Hv; Al = g_h0l[p] + (size_t)r0 * Hv; astr = Hv; }
            else if (seg == 2) { Ah = g_h1h[p] + (size_t)r0 * Hv; Al = g_h1l[p] + (size_t)r0 * Hv; astr = Hv; }
            else { Ah = g_xh + ((size_t)r0 * Tv + w) * Hv; Al = g_xl + ((size_t)r0 * Tv + w) * Hv; astr = (size_t)Tv * Hv; }

            auto load_chunk = [&](int b, int c) {
                load_tile(sb + OFF_AH(b), Ah + c * 64, astr);
                load_tile(sb + OFF_AL(b), Al + c * 64, astr);
                load_tile(sb + OFF_WL(b), Wlb + c * 64, Hv);
                asm volatile("cp.async.commit_group;" ::: "memory");
            };

            float acc[8][4];   // [mtile*4 + ntile][regs]
#pragma unroll
            for (int i = 0; i < 8; i++)
#pragma unroll
                for (int q = 0; q < 4; q++) acc[i][q] = 0.f;

            load_chunk(0, 0);
            load_chunk(1, 1);

#pragma unroll 1
            for (int c = 0; c < 16; c++) {
                const int b = c & 1;
                if (c < 15) asm volatile("cp.async.wait_group 1;" ::: "memory");
                else        asm volatile("cp.async.wait_group 0;" ::: "memory");
                __syncthreads();

                const uint32_t sWr = sb + OFF_WRES + c * 8192;
                const uint32_t sAh = sb + OFF_AH(b);
                const uint32_t sAl = sb + OFF_AL(b);
                const uint32_t sWl = sb + OFF_WL(b);
#pragma unroll
                for (int kq = 0; kq < 2; kq++) {
                    const int kk = khalf * 2 + kq;
                    uint32_t ka = ((uint32_t)(kk * 32 + koffA)) ^ xorA;
                    uint32_t kw = ((uint32_t)(kk * 32 + koffW)) ^ xorW;
                    uint32_t ah0[4], ah1[4], al0[4], al1[4], wh[8], wl[8];
                    ldm4(ah0, sAh + abase0 + ka);
                    ldm4(ah1, sAh + abase1 + ka);
                    ldm4(al0, sAl + abase0 + ka);
                    ldm4(al1, sAl + abase1 + ka);
                    ldm4(wh,     sWr + wbase0 + kw);
                    ldm4(wh + 4, sWr + wbase1 + kw);
                    ldm4(wl,     sWl + wbase0 + kw);
                    ldm4(wl + 4, sWl + wbase1 + kw);
#pragma unroll
                    for (int i = 0; i < 2; i++) {
                        const uint32_t* ah = i ? ah1 : ah0;
                        const uint32_t* al = i ? al1 : al0;
#pragma unroll
                        for (int j = 0; j < 4; j++) {
                            const uint32_t* bh = &wh[(j >> 1) * 4 + (j & 1) * 2];
                            const uint32_t* bl = &wl[(j >> 1) * 4 + (j & 1) * 2];
                            float* a_ = acc[i * 4 + j];
                            mma16816(a_, ah, bh);
                            mma16816(a_, al, bh);
                            mma16816(a_, ah, bl);
                        }
                    }
                }
                __syncthreads();
                if (c + 2 < 16) load_chunk(b, c + 2);
            }

            // ---- combine khalves via smem, write C tile ----
            float* cmb = (float*)(smem + OFF_CMB + tw * 4096);
            if (khalf) {
#pragma unroll
                for (int r = 0; r < 32; r++)
                    cmb[r * 32 + lane] = acc[r >> 2][r & 3];
            }
            __syncthreads();
            if (!khalf) {
                const int g = lane >> 2, tq = lane & 3;
#pragma unroll
                for (int i = 0; i < 2; i++) {
                    float* Cb = g_C + (size_t)(r0 + wr * 32 + i * 16 + g) * 4096
                              + ctc * 64 + wc * 32 + tq * 2;
#pragma unroll
                    for (int j = 0; j < 4; j++) {
                        int t = i * 4 + j;
                        float2 v0, v1;
                        v0.x = acc[t][0] + cmb[(t * 4 + 0) * 32 + lane];
                        v0.y = acc[t][1] + cmb[(t * 4 + 1) * 32 + lane];
                        v1.x = acc[t][2] + cmb[(t * 4 + 2) * 32 + lane];
                        v1.y = acc[t][3] + cmb[(t * 4 + 3) * 32 + lane];
                        *(float2*)(Cb + j * 8) = v0;
                        *(float2*)(Cb + 8 * 4096 + j * 8) = v1;
                    }
                }
            }
        }
        gbar(++expect);

        // ---------------- finalize ----------------
        {
            int idx = gid;
            int bb = idx >> 8;
            int j  = (idx & 255) << 2;
            const float* Crow = g_C + (size_t)bb * 4096 + j;

            if (w < Tv) {
                float4 c0 = __ldcg((const float4*)(Crow));
                float4 c3 = __ldcg((const float4*)(Crow + 3072));
                float4 bs = *(const float4*)&g_bsum[j];
                float4 hv;
                hv.x = tanhf(c0.x + c3.x + bs.x);
                hv.y = tanhf(c0.y + c3.y + bs.y);
                hv.z = tanhf(c0.z + c3.z + bs.z);
                hv.w = tanhf(c0.w + c3.w + bs.w);
                uint2 uh, ul;
                split4(hv, uh, ul);
                *(uint2*)&g_h0h[p ^ 1][bb * Hv + j] = uh;
                *(uint2*)&g_h0l[p ^ 1][bb * Hv + j] = ul;
                if (w == Tv - 1 && has_hn)
                    *(float4*)&out[(size_t)Bv * Tv * Hv + (size_t)bb * 2 * Hv + j] = hv;
            }
            if (w >= 1) {
                float4 c1 = __ldcg((const float4*)(Crow + 1024));
                float4 c2 = __ldcg((const float4*)(Crow + 2048));
                float4 bs = *(const float4*)&g_bsum[Hv + j];
                float4 hv;
                hv.x = tanhf(c1.x + c2.x + bs.x);
                hv.y = tanhf(c1.y + c2.y + bs.y);
                hv.z = tanhf(c1.z + c2.z + bs.z);
                hv.w = tanhf(c1.w + c2.w + bs.w);
                uint2 uh, ul;
                split4(hv, uh, ul);
                *(uint2*)&g_h1h[p ^ 1][bb * Hv + j] = uh;
                *(uint2*)&g_h1l[p ^ 1][bb * Hv + j] = ul;
                *(float4*)&out[(size_t)bb * Tv * Hv + (size_t)(w - 1) * Hv + j] = hv;
                if (w == Tv && has_hn)
                    *(float4*)&out[(size_t)Bv * Tv * Hv + (size_t)bb * 2 * Hv + Hv + j] = hv;
            }
        }
        gbar(++expect);
    }
}

// ---------------- launcher -----------------------------------------------------------
extern "C" void kernel_launch(void* const* d_in, const int* in_sizes, int n_in,
                              void* d_out, int out_size)
{
    (void)in_sizes; (void)n_in;
    const float* x  = (const float*)d_in[0];
    const float* h0 = (const float*)d_in[1];
    const float* Wi = (const float*)d_in[2];
    const float* bi = (const float*)d_in[3];
    const float* Wh = (const float*)d_in[4];
    const float* bh = (const float*)d_in[5];
    float* out = (float*)d_out;

    cudaFuncSetAttribute(k_persist, cudaFuncAttributeMaxDynamicSharedMemorySize, SMEM_SZ);

    int has_hn = (out_size >= Bv * Tv * Hv + Bv * 2 * Hv) ? 1 : 0;

    k_init<<<512, 256>>>(h0, bi, bh);
    k_splitx<<<32768, 256>>>(x);
    k_splitw<<<dim3(32, 32, 4), dim3(32, 8)>>>(Wi, Wh);
    k_persist<<<GRID, NTHR, SMEM_SZ>>>(out, has_hn);
}